// round 17
// baseline (speedup 1.0000x reference)
#include <cuda_runtime.h>
#include <cuda_bf16.h>
#include <math.h>

typedef unsigned long long ull;

// ---------------- problem constants ----------------
#define BB 64
#define SS 8
#define TT 8192
#define L1_LEN 8190
#define L2_LEN 8184
#define L3_LEN 8166

// ---------------- packed f32x2 helpers ----------------
__device__ __forceinline__ ull pk2(float lo, float hi) {
    ull r; asm("mov.b64 %0, {%1, %2};" : "=l"(r) : "f"(lo), "f"(hi)); return r;
}
__device__ __forceinline__ void up2(ull v, float& lo, float& hi) {
    asm("mov.b64 {%0, %1}, %2;" : "=f"(lo), "=f"(hi) : "l"(v));
}
__device__ __forceinline__ void fma2(ull& d, ull a, ull b) {
    asm("fma.rn.f32x2 %0, %1, %2, %0;" : "+l"(d) : "l"(a), "l"(b));
}

// ---------------- device scratch ----------------
__device__ float g_x0[(size_t)BB * 8  * TT];
__device__ float g_x3[(size_t)BB * 16 * TT];
__device__ float g_nx[BB * 16];
__device__ float g_nst2[BB * SS * 16];
__device__ float g_dot[(size_t)BB * SS * 256];

// ---------------- kernel 1: eeg 1x1 head (64 -> 8) ----------------
__global__ void k_head(const float* __restrict__ eeg,
                       const float* __restrict__ w,
                       const float* __restrict__ bias)
{
    __shared__ float sh_w[512];
    __shared__ float sh_b[8];
    int tid = threadIdx.x;
    for (int i = tid; i < 512; i += 256) sh_w[i] = w[i];
    if (tid < 8) sh_b[tid] = bias[tid];
    __syncthreads();

    size_t idx = (size_t)blockIdx.x * 256 + tid;
    int b = (int)(idx >> 13);
    int t = (int)(idx & (TT - 1));

    const float4* ep = (const float4*)(eeg + idx * 64);
    float acc[8];
#pragma unroll
    for (int c = 0; c < 8; c++) acc[c] = sh_b[c];
#pragma unroll
    for (int q = 0; q < 16; q++) {
        float4 v = ep[q];
#pragma unroll
        for (int c = 0; c < 8; c++) {
            acc[c] += v.x * sh_w[c * 64 + q * 4 + 0]
                    + v.y * sh_w[c * 64 + q * 4 + 1]
                    + v.z * sh_w[c * 64 + q * 4 + 2]
                    + v.w * sh_w[c * 64 + q * 4 + 3];
        }
    }
    float* ob = g_x0 + ((size_t)b * 8) * TT + t;
#pragma unroll
    for (int c = 0; c < 8; c++) ob[(size_t)c * TT] = acc[c];
}

// ---------------- R13 conv body (float shared, eeg stack only) ----------------
template <int CIN, int DIL, int NT>
__device__ __forceinline__ void conv_layer_s(const float* __restrict__ src, int sp,
                                             float* __restrict__ dst, int dp,
                                             const float* __restrict__ w,
                                             const ull* __restrict__ bp,
                                             int len, int tid)
{
    int items = 4 * ((len + 3) >> 2);
    for (int it = tid; it < items; it += NT) {
        int cg = it & 3;
        int p  = (it >> 2) * 4;
        ull b01 = bp[cg * 2], b23 = bp[cg * 2 + 1];
        ull a0[4], a1[4];
#pragma unroll
        for (int t = 0; t < 4; t++) { a0[t] = b01; a1[t] = b23; }
#pragma unroll
        for (int ci = 0; ci < CIN; ci++) {
#pragma unroll
            for (int k = 0; k < 3; k++) {
                const ull* wp = (const ull*)&w[(ci * 3 + k) * 16 + cg * 4];
                ull w01 = wp[0], w23 = wp[1];
                const float* xr = &src[ci * sp + p + k * DIL];
#pragma unroll
                for (int t = 0; t < 4; t++) {
                    ull x2 = pk2(xr[t], xr[t]);
                    fma2(a0[t], w01, x2);
                    fma2(a1[t], w23, x2);
                }
            }
        }
        int c0 = cg * 4;
#pragma unroll
        for (int t = 0; t < 4; t++) {
            if (p + t < len) {
                float l, h;
                up2(a0[t], l, h);
                dst[(c0 + 0) * dp + p + t] = fmaxf(l, 0.f);
                dst[(c0 + 1) * dp + p + t] = fmaxf(h, 0.f);
                up2(a1[t], l, h);
                dst[(c0 + 2) * dp + p + t] = fmaxf(l, 0.f);
                dst[(c0 + 3) * dp + p + t] = fmaxf(h, 0.f);
            }
        }
    }
}

// ---------------- kernel 2: fused eeg dilated stack (R15, unchanged) ----------------
#define EP1 284
#define EP2 284
__global__ void __launch_bounds__(128)
k_eeg_stack(const float* __restrict__ w1, const float* __restrict__ b1,
            const float* __restrict__ w2, const float* __restrict__ b2,
            const float* __restrict__ w3, const float* __restrict__ b3)
{
    __shared__ __align__(16) float sA[16 * EP1];
    __shared__ __align__(16) float sB[16 * EP2];
    __shared__ __align__(16) float sw1[384], sw2[768], sw3[768];
    __shared__ ull bp1[8], bp2[8], bp3[8];

    int b  = blockIdx.y;
    int t0 = blockIdx.x * 256;
    int tid = threadIdx.x;
    int nOut = min(256, L3_LEN - t0);
    int n2 = nOut + 18, n1 = nOut + 24, nIn = nOut + 26;

    for (int i = tid; i < 384; i += 128) {
        int co = i & 15; int rem = i >> 4; int k = rem % 3; int ci = rem / 3;
        sw1[i] = w1[(co * 8 + ci) * 3 + k];
    }
    for (int i = tid; i < 768; i += 128) {
        int co = i & 15; int rem = i >> 4; int k = rem % 3; int ci = rem / 3;
        sw2[i] = w2[(co * 16 + ci) * 3 + k];
        sw3[i] = w3[(co * 16 + ci) * 3 + k];
    }
    if (tid < 8) {
        bp1[tid] = pk2(b1[2 * tid], b1[2 * tid + 1]);
        bp2[tid] = pk2(b2[2 * tid], b2[2 * tid + 1]);
        bp3[tid] = pk2(b3[2 * tid], b3[2 * tid + 1]);
    }

    const float* inb = g_x0 + ((size_t)b * 8) * TT + t0;
    for (int i = tid; i < 8 * nIn; i += 128) {
        int ci = i / nIn, q = i - ci * nIn;
        sB[ci * EP2 + q] = (t0 + q < TT) ? inb[(size_t)ci * TT + q] : 0.f;
    }
    __syncthreads();

    conv_layer_s<8, 1, 128>(sB, EP2, sA, EP1, sw1, bp1, n1, tid);
    __syncthreads();
    conv_layer_s<16, 3, 128>(sA, EP1, sB, EP2, sw2, bp2, n2, tid);
    __syncthreads();

    {
        float* ob = g_x3 + ((size_t)b * 16) * TT + t0;
        int items = 4 * ((nOut + 3) >> 2);
        for (int it = tid; it < items; it += 128) {
            int cg = it & 3;
            int p  = (it >> 2) * 4;
            ull b01 = bp3[cg * 2], b23 = bp3[cg * 2 + 1];
            ull a0[4], a1[4];
#pragma unroll
            for (int t = 0; t < 4; t++) { a0[t] = b01; a1[t] = b23; }
#pragma unroll
            for (int ci = 0; ci < 16; ci++) {
#pragma unroll
                for (int k = 0; k < 3; k++) {
                    const ull* wp = (const ull*)&sw3[(ci * 3 + k) * 16 + cg * 4];
                    ull w01 = wp[0], w23 = wp[1];
                    const float* xr = &sB[ci * EP2 + p + k * 9];
#pragma unroll
                    for (int t = 0; t < 4; t++) {
                        ull x2 = pk2(xr[t], xr[t]);
                        fma2(a0[t], w01, x2);
                        fma2(a1[t], w23, x2);
                    }
                }
            }
            float lo[4], hi[4], lo2[4], hi2[4];
#pragma unroll
            for (int t = 0; t < 4; t++) { up2(a0[t], lo[t], hi[t]); up2(a1[t], lo2[t], hi2[t]); }
            int c0 = cg * 4;
            if (p + 3 < nOut) {
                *(float4*)&ob[(size_t)(c0 + 0) * TT + p] =
                    make_float4(fmaxf(lo[0],0.f), fmaxf(lo[1],0.f), fmaxf(lo[2],0.f), fmaxf(lo[3],0.f));
                *(float4*)&ob[(size_t)(c0 + 1) * TT + p] =
                    make_float4(fmaxf(hi[0],0.f), fmaxf(hi[1],0.f), fmaxf(hi[2],0.f), fmaxf(hi[3],0.f));
                *(float4*)&ob[(size_t)(c0 + 2) * TT + p] =
                    make_float4(fmaxf(lo2[0],0.f), fmaxf(lo2[1],0.f), fmaxf(lo2[2],0.f), fmaxf(lo2[3],0.f));
                *(float4*)&ob[(size_t)(c0 + 3) * TT + p] =
                    make_float4(fmaxf(hi2[0],0.f), fmaxf(hi2[1],0.f), fmaxf(hi2[2],0.f), fmaxf(hi2[3],0.f));
            } else {
                for (int t = 0; t < 4; t++) {
                    if (p + t < nOut) {
                        ob[(size_t)(c0 + 0) * TT + p + t] = fmaxf(lo[t],  0.f);
                        ob[(size_t)(c0 + 1) * TT + p + t] = fmaxf(hi[t],  0.f);
                        ob[(size_t)(c0 + 2) * TT + p + t] = fmaxf(lo2[t], 0.f);
                        ob[(size_t)(c0 + 3) * TT + p + t] = fmaxf(hi2[t], 0.f);
                    }
                }
            }
        }
    }
}

// ---------------- kernel 3: eeg row norms ----------------
__global__ void k_eegnorm()
{
    __shared__ float red[256];
    int r = blockIdx.x;
    int tid = threadIdx.x;
    const float* p = g_x3 + (size_t)r * TT;
    float ss = 0.f;
    for (int t = tid; t < L3_LEN; t += 256) { float v = p[t]; ss += v * v; }
    red[tid] = ss; __syncthreads();
    for (int st = 128; st > 0; st >>= 1) {
        if (tid < st) red[tid] += red[tid + st];
        __syncthreads();
    }
    if (tid == 0) g_nx[r] = fmaxf(sqrtf(red[0]), 1e-8f);
}

// ---------------- kernel 4: zero accumulators ----------------
__global__ void k_zero()
{
    int i = blockIdx.x * 256 + threadIdx.x;
    if (i < BB * SS * 256) g_dot[i] = 0.f;
    if (i < BB * SS * 16)  g_nst2[i] = 0.f;
}

// ---------------- time-packed conv (dual-copy src, f32x2 time pairs) ----------------
template <int DIL, int SPu, int DP, int DLEN, bool DUPOUT>
__device__ __forceinline__ void conv_tp(const ull* __restrict__ XAu,
                                        const ull* __restrict__ XBu,
                                        const ull* __restrict__ wd,   // dup weights
                                        const ull* __restrict__ bd,   // dup bias
                                        float* __restrict__ dstA,
                                        float* __restrict__ dstB,
                                        int items, int tid)
{
    for (int it = tid; it < items; it += 128) {
        int cg = it & 3;
        int t0 = (it >> 2) * 8;
        ulonglong2 bb01 = *(const ulonglong2*)(bd + cg * 4);
        ulonglong2 bb23 = *(const ulonglong2*)(bd + cg * 4 + 2);
        ull acc0[4], acc1[4], acc2[4], acc3[4];
#pragma unroll
        for (int u = 0; u < 4; u++) {
            acc0[u] = bb01.x; acc1[u] = bb01.y;
            acc2[u] = bb23.x; acc3[u] = bb23.y;
        }
#pragma unroll
        for (int ci = 0; ci < 16; ci++) {
#pragma unroll
            for (int k = 0; k < 3; k++) {
                const int kd = k * DIL;
                ulonglong2 w01 = *(const ulonglong2*)(wd + (ci * 3 + k) * 16 + cg * 4);
                ulonglong2 w23 = *(const ulonglong2*)(wd + (ci * 3 + k) * 16 + cg * 4 + 2);
                const ull* xp = (kd & 1)
                    ? (XBu + ci * SPu + ((t0 + kd - 1) >> 1))
                    : (XAu + ci * SPu + ((t0 + kd) >> 1));
                ull x0 = xp[0], x1 = xp[1], x2 = xp[2], x3 = xp[3];
                fma2(acc0[0], w01.x, x0); fma2(acc0[1], w01.x, x1);
                fma2(acc0[2], w01.x, x2); fma2(acc0[3], w01.x, x3);
                fma2(acc1[0], w01.y, x0); fma2(acc1[1], w01.y, x1);
                fma2(acc1[2], w01.y, x2); fma2(acc1[3], w01.y, x3);
                fma2(acc2[0], w23.x, x0); fma2(acc2[1], w23.x, x1);
                fma2(acc2[2], w23.x, x2); fma2(acc2[3], w23.x, x3);
                fma2(acc3[0], w23.y, x0); fma2(acc3[1], w23.y, x1);
                fma2(acc3[2], w23.y, x2); fma2(acc3[3], w23.y, x3);
            }
        }
#pragma unroll
        for (int j = 0; j < 4; j++) {
            int co = cg * 4 + j;
#pragma unroll
            for (int u = 0; u < 4; u++) {
                ull a = (j == 0) ? acc0[u] : (j == 1) ? acc1[u] : (j == 2) ? acc2[u] : acc3[u];
                float lo, hi;
                up2(a, lo, hi);
                lo = fmaxf(lo, 0.f); hi = fmaxf(hi, 0.f);
                int t = t0 + 2 * u;
                if (DUPOUT) {
                    if (t < DLEN) {
                        dstA[co * DP + t] = lo;
                        if (t > 0) dstB[co * DP + t - 1] = lo;
                    }
                    if (t + 1 < DLEN) {
                        dstA[co * DP + t + 1] = hi;
                        dstB[co * DP + t] = hi;
                    }
                } else {
                    dstA[co * DP + t]     = lo;
                    dstA[co * DP + t + 1] = hi;
                }
            }
        }
    }
}

// ---------------- kernel 5: stim stack + dot, time-packed, dynamic smem ----------------
#define PINs 284
#define PAf  288
#define PAu  144
#define PBf  276
#define PBu  138
#define P3f  260
// dyn smem offsets (bytes)
#define OFF_XB1  18432
#define OFF_XA2  36864
#define OFF_XB2  54528
#define OFF_IN   72192
#define OFF_WD2  73344
#define OFF_WD3  79488
#define OFF_BD2  85632
#define OFF_BD3  85760
#define OFF_W1   85888
#define OFF_B1   86080
#define DSMEM    86144

__global__ void __launch_bounds__(128)
k_stim(const float* __restrict__ stim,
       const float* __restrict__ ws1, const float* __restrict__ bs1,
       const float* __restrict__ ws2, const float* __restrict__ bs2,
       const float* __restrict__ ws3, const float* __restrict__ bs3)
{
    extern __shared__ __align__(16) char dyn[];
    float* XA1f = (float*)(dyn);
    float* XB1f = (float*)(dyn + OFF_XB1);
    float* XA2f = (float*)(dyn + OFF_XA2);
    float* XB2f = (float*)(dyn + OFF_XB2);
    float* shin = (float*)(dyn + OFF_IN);
    ull*   wd2  = (ull*)(dyn + OFF_WD2);
    ull*   wd3  = (ull*)(dyn + OFF_WD3);
    ull*   bd2  = (ull*)(dyn + OFF_BD2);
    ull*   bd3  = (ull*)(dyn + OFF_BD3);
    float* sw1  = (float*)(dyn + OFF_W1);
    float* sb1  = (float*)(dyn + OFF_B1);
    const ull* XA1u = (const ull*)XA1f;
    const ull* XB1u = (const ull*)XB1f;
    const ull* XA2u = (const ull*)XA2f;
    const ull* XB2u = (const ull*)XB2f;
    float* l3f = XA1f;              // after l1 dead
    float* xsf = XB1f;              // after l1 dead

    int bx = blockIdx.x;
    int n  = bx >> 2;               // n = s*B + b
    int cb = bx & 3;
    int s  = n >> 6;
    int b  = n & 63;
    int tid = threadIdx.x;

    if (tid < 48) { int co = tid & 15, k = tid >> 4; sw1[k * 16 + co] = ws1[co * 3 + k]; }
    if (tid < 16) sb1[tid] = bs1[tid];
    for (int i = tid; i < 768; i += 128) {
        int co = i & 15; int rem = i >> 4; int k = rem % 3; int ci = rem / 3;
        float v2 = ws2[(co * 16 + ci) * 3 + k];
        float v3 = ws3[(co * 16 + ci) * 3 + k];
        wd2[i] = pk2(v2, v2);
        wd3[i] = pk2(v3, v3);
    }
    if (tid < 16) {
        float v2 = bs2[tid], v3 = bs3[tid];
        bd2[tid] = pk2(v2, v2);
        bd3[tid] = pk2(v3, v3);
    }

    const float* seq   = stim + ((size_t)(b * SS + s)) * TT;
    const float* xbase = g_x3 + ((size_t)b * 16) * TT;

    int chunk = tid >> 6;
    int q = tid & 63;
    int ip = q >> 3, jp = q & 7;
    int i0 = ip * 2, j0 = jp * 2;
    const ull* A0 = (const ull*)(l3f + (i0 + 0) * P3f);
    const ull* A1 = (const ull*)(l3f + (i0 + 1) * P3f);
    const ull* B0 = (const ull*)(xsf + (j0 + 0) * P3f);
    const ull* B1 = (const ull*)(xsf + (j0 + 1) * P3f);

    ull c00 = 0, c01 = 0, c10 = 0, c11 = 0, ss0 = 0, ss1 = 0;

    for (int tile = cb * 8; tile < cb * 8 + 8; tile++) {
        int t0 = tile * 256;
        int nOut = min(256, L3_LEN - t0);

        for (int i = tid; i < PINs; i += 128)
            shin[i] = (t0 + i < TT) ? seq[t0 + i] : 0.f;
        __syncthreads();   // ends prev dot (XA1/XB1 safe) + shin ready

        // layer 1: 1->16, dil 1, fixed len 280, zero-extended to 288; dual copy
        for (int c = 0; c < 16; c++) {
            float wa = sw1[c], wb = sw1[16 + c], wc = sw1[32 + c], bb = sb1[c];
            for (int qq = tid; qq < PAf; qq += 128) {
                float v = 0.f;
                if (qq < 280)
                    v = fmaxf(bb + shin[qq] * wa + shin[qq + 1] * wb + shin[qq + 2] * wc, 0.f);
                XA1f[c * PAf + qq] = v;
                if (qq > 0) XB1f[c * PAf + qq - 1] = v;
            }
        }
        __syncthreads();

        // layer 2: 16->16, dil 3, outputs 274; dual copy
        conv_tp<3, PAu, PBf, 274, true>(XA1u, XB1u, wd2, bd2, XA2f, XB2f, 140, tid);
        __syncthreads();

        // layer 3: 16->16, dil 9, outputs exactly 256; plain float into l3f
        conv_tp<9, PBu, P3f, 256, false>(XA2u, XB2u, wd3, bd3, l3f, (float*)0, 128, tid);
        __syncthreads();

        // eeg x tile into xsf
        for (int i = tid; i < 16 * 256; i += 128) {
            int j = i >> 8, t = i & 255;
            if (t < nOut) xsf[j * P3f + t] = xbase[(size_t)j * TT + t0 + t];
        }
        __syncthreads();

        // dot accumulate (registers persist across tiles)
        int tBeg = chunk * 128;
        int tEnd = min(tBeg + 128, nOut);
        for (int t2 = tBeg >> 1; t2 < (tEnd >> 1); t2++) {
            ull a0 = A0[t2], a1 = A1[t2], b0 = B0[t2], b1 = B1[t2];
            fma2(c00, a0, b0); fma2(c01, a0, b1);
            fma2(c10, a1, b0); fma2(c11, a1, b1);
            if (jp == 0) { fma2(ss0, a0, a0); fma2(ss1, a1, a1); }
        }
        // no sync: next tile's first sync orders dot-reads vs l1 writes
    }

    // combine across chunk-blocks via atomics
    {
        float l, h;
        float* gd = g_dot + (size_t)n * 256;
        up2(c00, l, h); atomicAdd(&gd[(i0 + 0) * 16 + j0 + 0], l + h);
        up2(c01, l, h); atomicAdd(&gd[(i0 + 0) * 16 + j0 + 1], l + h);
        up2(c10, l, h); atomicAdd(&gd[(i0 + 1) * 16 + j0 + 0], l + h);
        up2(c11, l, h); atomicAdd(&gd[(i0 + 1) * 16 + j0 + 1], l + h);
        if (jp == 0) {
            up2(ss0, l, h); atomicAdd(&g_nst2[n * 16 + i0 + 0], l + h);
            up2(ss1, l, h); atomicAdd(&g_nst2[n * 16 + i0 + 1], l + h);
        }
    }
}

// ---------------- kernel 6: finalize cosine + linear ----------------
__global__ void k_final(const float* __restrict__ w_lin,
                        const float* __restrict__ b_lin,
                        float* __restrict__ out)
{
    __shared__ float red[256];
    int n = blockIdx.x;
    int s = n >> 6;
    int b = n & 63;
    int tid = threadIdx.x;
    int i = tid >> 4, j = tid & 15;

    float ni = fmaxf(sqrtf(g_nst2[n * 16 + i]), 1e-8f);
    float nj = g_nx[b * 16 + j];
    float v  = w_lin[tid] * g_dot[(size_t)n * 256 + tid] / (ni * nj);

    red[tid] = v; __syncthreads();
    for (int st = 128; st > 0; st >>= 1) {
        if (tid < st) red[tid] += red[tid + st];
        __syncthreads();
    }
    if (tid == 0) out[b * SS + s] = red[0] + b_lin[0];
}

// ---------------- launch ----------------
extern "C" void kernel_launch(void* const* d_in, const int* in_sizes, int n_in,
                              void* d_out, int out_size)
{
    const float* eeg   = (const float*)d_in[0];
    const float* stim  = (const float*)d_in[1];
    const float* w_eeg = (const float*)d_in[2];
    const float* b_eeg = (const float*)d_in[3];
    const float* w_e1  = (const float*)d_in[4];
    const float* b_e1  = (const float*)d_in[5];
    const float* w_e2  = (const float*)d_in[6];
    const float* b_e2  = (const float*)d_in[7];
    const float* w_e3  = (const float*)d_in[8];
    const float* b_e3  = (const float*)d_in[9];
    const float* w_s1  = (const float*)d_in[10];
    const float* b_s1  = (const float*)d_in[11];
    const float* w_s2  = (const float*)d_in[12];
    const float* b_s2  = (const float*)d_in[13];
    const float* w_s3  = (const float*)d_in[14];
    const float* b_s3  = (const float*)d_in[15];
    const float* w_lin = (const float*)d_in[16];
    const float* b_lin = (const float*)d_in[17];
    float* out = (float*)d_out;

    static int smem_set = 0;
    if (!smem_set) {
        cudaFuncSetAttribute(k_stim, cudaFuncAttributeMaxDynamicSharedMemorySize, DSMEM);
        smem_set = 1;
    }

    k_head<<<(BB * TT) / 256, 256>>>(eeg, w_eeg, b_eeg);
    k_eeg_stack<<<dim3(32, BB), 128>>>(w_e1, b_e1, w_e2, b_e2, w_e3, b_e3);
    k_eegnorm<<<BB * 16, 256>>>();

    k_zero<<<(BB * SS * 256) / 256, 256>>>();

    k_stim<<<BB * SS * 4, 128, DSMEM>>>(stim, w_s1, b_s1, w_s2, b_s2, w_s3, b_s3);

    k_final<<<BB * SS, 256>>>(w_lin, b_lin, out);
}